// round 14
// baseline (speedup 1.0000x reference)
#include <cuda_runtime.h>
#include <math.h>

#define NB 8
#define CC 3
#define HH 512
#define WW 512
#define HY 256
#define WY 256
#define GG 5
#define MM 3
#define LOG2E 1.4426950408889634f

// ---------------- parameter block (device-computed -> __constant__) ----------------
// Expanded-quadratic logit: lg = a + x0*(b0 + q00 x0 + q01 x1 + q02 x2)
//                              + x1*(b1 + q11 x1 + q12 x2) + x2*(b2 + q22 x2)
struct __align__(16) Prm {
    float4 qA[GG];        // {q00, q11, q22, q01}   (LOG2E-folded, -0.5 folded)
    float4 qB[GG];        // {q02, q12, b0,  b1 }
    float4 qC[GG];        // {b2,  a,   0,   0  }
    float4 mf[GG*MM];     // {c, aL, aR, 0} with a = sqrt(0.5*LOG2E)/sigma
    float  we[4];         // even-row upsample taps (x2 folded)
    float  wo[4];         // odd-row upsample taps  (x2 folded)
};

__constant__ Prm c_prm;
__device__   Prm g_prm;
__device__ float g_y[NB*CC*HY*WY];   // downsampled pyramid level (6.3 MB)

__device__ __forceinline__ float softplus_f(float x){
    if (x > 20.f) return x;
    return log1pf(__expf(x));
}
__device__ __forceinline__ float ex2f(float x){
    float y; asm("ex2.approx.ftz.f32 %0, %1;" : "=f"(y) : "f"(x)); return y;
}

__device__ __forceinline__ void gauss7(float* gw){
    float s = 0.f;
    #pragma unroll
    for (int k = 0; k < 7; k++){
        float r = (float)(k - 3);
        gw[k] = __expf(-r*r/(2.f*0.9f*0.9f));
        s += gw[k];
    }
    float is = 1.f/s;
    #pragma unroll
    for (int k = 0; k < 7; k++) gw[k] *= is;
}

// ---------------- setup work (inside down_kernel's extra z-slice) ----------------
__device__ void do_setup(const float* __restrict__ mu,
                         const float* __restrict__ L_raw,
                         const float* __restrict__ pi,
                         const float* __restrict__ mf_c,
                         const float* __restrict__ mf_sL,
                         const float* __restrict__ mf_sR,
                         int t)
{
    float gw[7];
    gauss7(gw);

    if (t == 0){
        // 2D transposed-conv kernel is 4*(g outer g): fold sqrt(4)=2 into EACH 1D stage.
        g_prm.we[0]=2.f*gw[1]; g_prm.we[1]=2.f*gw[3]; g_prm.we[2]=2.f*gw[5]; g_prm.we[3]=0.f;
        g_prm.wo[0]=2.f*gw[0]; g_prm.wo[1]=2.f*gw[2]; g_prm.wo[2]=2.f*gw[4]; g_prm.wo[3]=2.f*gw[6];
    }

    if (t < GG){
        int g = t;
        float pmx = -3.4e38f;
        for (int q = 0; q < GG; q++) pmx = fmaxf(pmx, pi[q]);
        float ps = 0.f;
        for (int q = 0; q < GG; q++) ps += __expf(pi[q] - pmx);
        float lse = pmx + logf(ps);

        float L[3][3];
        for (int i = 0; i < 3; i++)
            for (int j = 0; j < 3; j++)
                L[i][j] = (j < i) ? L_raw[(g*3+i)*3+j] : 0.f;
        for (int i = 0; i < 3; i++)
            L[i][i] = softplus_f(softplus_f(L_raw[(g*3+i)*3+i]) + 1e-4f) + 1e-4f;

        float S[3][3];
        for (int i = 0; i < 3; i++)
            for (int j = 0; j < 3; j++){
                float acc = 0.f;
                for (int k = 0; k < 3; k++) acc += L[i][k]*L[j][k];
                S[i][j] = acc + (i==j ? 1e-4f : 0.f);
            }

        float detS = S[0][0]*(S[1][1]*S[2][2]-S[1][2]*S[1][2])
                   - S[0][1]*(S[0][1]*S[2][2]-S[1][2]*S[0][2])
                   + S[0][2]*(S[0][1]*S[1][2]-S[1][1]*S[0][2]);

        float A00=S[0][0]+1e-3f, A11=S[1][1]+1e-3f, A22=S[2][2]+1e-3f;
        float A01=S[0][1],       A02=S[0][2],       A12=S[1][2];
        float detA = A00*(A11*A22-A12*A12) - A01*(A01*A22-A12*A02) + A02*(A01*A12-A11*A02);
        float id = 1.f/detA;
        float i00 = (A11*A22-A12*A12)*id;
        float i11 = (A00*A22-A02*A02)*id;
        float i22 = (A00*A11-A01*A01)*id;
        float i01 = (A02*A12-A01*A22)*id;
        float i02 = (A01*A12-A02*A11)*id;
        float i12 = (A01*A02-A00*A12)*id;

        // LOG2E-folded coefficients (exp2 domain), -0.5 on diagonals, -1 on crosses
        float q00 = LOG2E*-0.5f*i00, q11 = LOG2E*-0.5f*i11, q22 = LOG2E*-0.5f*i22;
        float q01 = LOG2E*-i01,      q02 = LOG2E*-i02,      q12 = LOG2E*-i12;
        float cw  = LOG2E*(-0.5f*logf(detS) + (pi[g]-lse));
        float m0 = mu[g*3+0], m1 = mu[g*3+1], m2 = mu[g*3+2];

        // expand quadratic around 0: linear + constant terms
        float b0 = -(2.f*q00*m0 + q01*m1 + q02*m2);
        float b1 = -(2.f*q11*m1 + q01*m0 + q12*m2);
        float b2 = -(2.f*q22*m2 + q02*m0 + q12*m1);
        float a  = cw + q00*m0*m0 + q11*m1*m1 + q22*m2*m2
                 + q01*m0*m1 + q02*m0*m2 + q12*m1*m2;

        g_prm.qA[g] = make_float4(q00, q11, q22, q01);
        g_prm.qB[g] = make_float4(q02, q12, b0, b1);
        g_prm.qC[g] = make_float4(b2, a, 0.f, 0.f);
    }

    // membership params: a = sqrt(0.5*LOG2E)/sigma so e_m = exp2(-((r-c)*a)^2)
    if (t < GG*MM){
        float sc = sqrtf(0.5f*LOG2E);
        float sl = softplus_f(mf_sL[t]) + 1e-12f;
        float sr = softplus_f(mf_sR[t]) + 1e-12f;
        g_prm.mf[t] = make_float4(mf_c[t], sc/sl, sc/sr, 0.f);
    }
}

// ---------------- kernel 1: reflect-pad blur downsample (+ setup z-slice) ----------------
// tmp stored even/odd split so the horizontal stride-2 reads become stride-1
// (odd half base offset 1104 floats: 1104 mod 32 == 16 -> disjoint banks from even half)
#define TMP_O 1104
__global__ __launch_bounds__(256)
void down_kernel(const float* __restrict__ x,
                 const float* __restrict__ mu,
                 const float* __restrict__ L_raw,
                 const float* __restrict__ pi,
                 const float* __restrict__ mf_c,
                 const float* __restrict__ mf_sL,
                 const float* __restrict__ mf_sR)
{
    __shared__ __align__(16) float xs[37][140];
    __shared__ float tmp2[2224];   // E: r*68+qh ; O: TMP_O + r*68+qh

    int t  = threadIdx.x;
    int nc = blockIdx.z;

    if (nc == NB*CC){
        if (blockIdx.x == 0 && blockIdx.y == 0)
            do_setup(mu, L_raw, pi, mf_c, mf_sL, mf_sR, t);
        return;
    }

    int j0 = blockIdx.x * 64;
    int i0 = blockIdx.y * 16;
    const float* xb = x + (size_t)nc * (HH*WW);

    float w[7];
    gauss7(w);

    int r0 = 2*i0 - 3, c0 = 2*j0 - 3;
    int cbase = c0 & ~3;
    int shift = c0 - cbase;
    int lane = t & 31, wrp = t >> 5;

    bool fast = (r0 >= 0) && (r0 + 36 <= 511) && (cbase >= 0) && (cbase + 136 <= 512);

    if (fast){
        for (int idx = t; idx < 37*34; idx += 256){
            int ri = idx / 34, k = idx - ri*34;
            float4 v = __ldcs((const float4*)(xb + (size_t)(r0+ri)*WW + cbase + 4*k));
            *(float4*)&xs[ri][4*k] = v;
        }
    } else {
        for (int ri = wrp; ri < 37; ri += 8){
            int rr = r0 + ri; rr = (rr < 0) ? -rr : ((rr > 511) ? 1022 - rr : rr);
            const float* row = xb + (size_t)rr*WW;
            for (int ci = lane; ci < 133; ci += 32){
                int cc = c0 + ci; cc = (cc < 0) ? -cc : ((cc > 511) ? 1022 - cc : cc);
                xs[ri][ci + shift] = __ldcs(&row[cc]);
            }
        }
    }
    __syncthreads();

    // vertical 7-tap into even/odd-split tmp (warp-per-row, conflict-free STS)
    #pragma unroll
    for (int rep = 0; rep < 2; rep++){
        int r = wrp + 8*rep;
        for (int q = lane; q < 133; q += 32){
            float s = 0.f;
            #pragma unroll
            for (int a = 0; a < 7; a++) s += w[a]*xs[2*r+a][q + shift];
            int addr = ((q & 1) ? TMP_O : 0) + r*68 + (q >> 1);
            tmp2[addr] = s;
        }
    }
    __syncthreads();

    // horizontal 7-tap downsample: all reads stride-1 (E and O halves on disjoint banks)
    float* yb = g_y + (size_t)nc * (HY*WY);
    int jl = t & 63;
    int rb = t >> 6;
    #pragma unroll
    for (int rr = 0; rr < 4; rr++){
        int r = rb*4 + rr;
        const float* E = &tmp2[r*68];
        const float* O = &tmp2[TMP_O + r*68];
        float s = w[0]*E[jl]   + w[1]*O[jl]
                + w[2]*E[jl+1] + w[3]*O[jl+1]
                + w[4]*E[jl+2] + w[5]*O[jl+2]
                + w[6]*E[jl+3];
        yb[(i0+r)*WY + j0 + jl] = s;
    }
}

// ---------------- kernel 2: fused upsample + GMM (Horner) + membership ----------------
// Sequential row-pairing + precomputed flush slots + division-free (c,li) walks.
// __launch_bounds__(256,7): cap regs at 36 -> 7 blocks/SM (56 warps, 87.5% theoretical)
__global__ __launch_bounds__(256, 7)
void up_gmm_kernel(float* __restrict__ out)
{
    __shared__ float yt[3][19][20];               // y tile
    __shared__ float rs[3][19][32];               // horizontal upsample row sums
    __shared__ __align__(16) float stage[256*15]; // stride-15 staging (conflict-free)

    int tx = threadIdx.x, ty = threadIdx.y;
    int t  = ty*32 + tx;
    int v0 = blockIdx.x * 32;
    int u0 = blockIdx.y * 32;
    int n  = blockIdx.z;

    int iy0 = u0/2 - 1, jy0 = v0/2 - 1;

    // yt load: division-free (c,li) walk; lane = column (19 active)
    {
        int c = 0, li = ty;
        #pragma unroll
        for (int rep = 0; rep < 8; rep++){
            if (c < 3 && tx < 19){
                int gi = iy0 + li, gj = jy0 + tx;
                float v = 0.f;
                if ((unsigned)gi < 256u && (unsigned)gj < 256u)
                    v = g_y[((n*3 + c) << 16) + (gi << 8) + gj];
                yt[c][li][tx] = v;
            }
            li += 8; if (li >= 19){ li -= 19; c++; }
        }
    }
    __syncthreads();

    // rs pass: division-free (c,li) walk; lane = output col
    {
        int c = 0, li = ty;
        #pragma unroll
        for (int rep = 0; rep < 8; rep++){
            if (c < 3){
                int vl = tx;
                float s;
                if (vl & 1){
                    int lj = (vl - 1) >> 1;
                    s = c_prm.wo[0]*yt[c][li][lj]   + c_prm.wo[1]*yt[c][li][lj+1]
                      + c_prm.wo[2]*yt[c][li][lj+2] + c_prm.wo[3]*yt[c][li][lj+3];
                } else {
                    int lj = vl >> 1;
                    s = c_prm.we[0]*yt[c][li][lj] + c_prm.we[1]*yt[c][li][lj+1] + c_prm.we[2]*yt[c][li][lj+2];
                }
                rs[c][li][vl] = s;
            }
            li += 8; if (li >= 19){ li -= 19; c++; }
        }
    }
    __syncthreads();

    // ---- flush slots precomputed ONCE (identical for every slab/phase) ----
    int soff[4], goff[4], cnt = 0;
    {
        int r = t/120, c4 = t - (t/120)*120;
        while (r < 8){
            soff[cnt] = r*480 + c4*4;
            goff[cnt] = (2*r)*(512*15) + c4*4;
            cnt++;
            c4 += 16; r += 2;
            if (c4 >= 120){ c4 -= 120; r += 1; }
        }
    }
    float* st = &stage[t*15];

    #pragma unroll
    for (int slab = 0; slab < 2; slab++){
        int p = slab*8 + ty;      // pair: rows 2p (even), 2p+1 (odd)

        // shared vertical taps: 12 LDS serve both pixels of the pair
        float xe[3], xo[3];
        #pragma unroll
        for (int c = 0; c < 3; c++){
            float a0 = rs[c][p  ][tx];
            float a1 = rs[c][p+1][tx];
            float a2 = rs[c][p+2][tx];
            float a3 = rs[c][p+3][tx];
            xe[c] = c_prm.we[0]*a0 + c_prm.we[1]*a1 + c_prm.we[2]*a2;
            xo[c] = c_prm.wo[0]*a0 + c_prm.wo[1]*a1 + c_prm.wo[2]*a2 + c_prm.wo[3]*a3;
        }

        float* slabOut = out + (((size_t)(n*512 + u0 + slab*16))*512 + v0)*15;

        // two sequential phases through the same stage: even rows, then odd rows
        for (int phase = 0; phase < 2; phase++){
            float x0 = phase ? xo[0] : xe[0];
            float x1 = phase ? xo[1] : xe[1];
            float x2 = phase ? xo[2] : xe[2];

            // GMM logits: Horner-expanded quadratic (9 FMA each), exp2 domain
            float lg[GG];
            float mx = -3.4e38f;
            #pragma unroll
            for (int g = 0; g < GG; g++){
                float4 A = c_prm.qA[g], B = c_prm.qB[g], C = c_prm.qC[g];
                float t0 = fmaf(A.x, x0, B.z);
                t0 = fmaf(A.w, x1, t0);
                t0 = fmaf(B.x, x2, t0);
                float q = fmaf(x0, t0, C.y);
                float t1 = fmaf(A.y, x1, B.w);
                t1 = fmaf(B.y, x2, t1);
                q = fmaf(x1, t1, q);
                float t2 = fmaf(A.z, x2, C.x);
                q = fmaf(x2, t2, q);
                lg[g] = q;
                mx = fmaxf(mx, q);
            }
            float e[GG], ssum = 0.f;
            #pragma unroll
            for (int g = 0; g < GG; g++){ e[g] = ex2f(lg[g] - mx); ssum += e[g]; }
            float inv = __fdividef(1.0f, ssum);

            // membership: direct evaluation, staged to smem
            #pragma unroll
            for (int g = 0; g < GG; g++){
                float r = e[g]*inv;
                float es[MM], s2 = 0.f;
                #pragma unroll
                for (int m = 0; m < MM; m++){
                    float4 pm = c_prm.mf[g*MM+m];
                    float a = (r < pm.x) ? pm.y : pm.z;
                    float d = (r - pm.x)*a;
                    es[m] = ex2f(-d*d);
                    s2 += es[m];
                }
                float inv2 = __fdividef(1.0f, s2);
                st[g*3+0] = es[0]*inv2;
                st[g*3+1] = es[1]*inv2;
                st[g*3+2] = es[2]*inv2;
            }
            __syncthreads();

            // coalesced streaming flush via precomputed slots
            float* baseOut = slabOut + (size_t)phase*(512*15);
            #pragma unroll
            for (int i = 0; i < 4; i++){
                if (i < cnt)
                    __stcs((float4*)(baseOut + goff[i]),
                           *(const float4*)&stage[soff[i]]);
            }
            __syncthreads();
        }
    }
}

// ---------------- launch ----------------
extern "C" void kernel_launch(void* const* d_in, const int* in_sizes, int n_in,
                              void* d_out, int out_size)
{
    (void)in_sizes; (void)n_in; (void)out_size;
    const float* x     = (const float*)d_in[0];
    const float* mu    = (const float*)d_in[1];
    const float* L_raw = (const float*)d_in[2];
    const float* pi    = (const float*)d_in[3];
    const float* mf_c  = (const float*)d_in[4];
    const float* mf_sL = (const float*)d_in[5];
    const float* mf_sR = (const float*)d_in[6];
    float* out = (float*)d_out;

    down_kernel<<<dim3(WY/64, HY/16, NB*CC + 1), 256>>>(x, mu, L_raw, pi, mf_c, mf_sL, mf_sR);

    void* src = nullptr;
    cudaGetSymbolAddress(&src, g_prm);
    cudaMemcpyToSymbolAsync(c_prm, src, sizeof(Prm), 0, cudaMemcpyDeviceToDevice, 0);

    up_gmm_kernel<<<dim3(WW/32, HH/32, NB), dim3(32, 8)>>>(out);
}

// round 15
// speedup vs baseline: 1.1412x; 1.1412x over previous
#include <cuda_runtime.h>
#include <math.h>

#define NB 8
#define CC 3
#define HH 512
#define WW 512
#define HY 256
#define WY 256
#define GG 5
#define MM 3
#define LOG2E 1.4426950408889634f

// ---------------- parameter block (device-computed -> __constant__) ----------------
// Expanded-quadratic logit: lg = a + x0*(b0 + q00 x0 + q01 x1 + q02 x2)
//                              + x1*(b1 + q11 x1 + q12 x2) + x2*(b2 + q22 x2)
struct __align__(16) Prm {
    float4 qA[GG];        // {q00, q11, q22, q01}   (LOG2E-folded, -0.5 folded)
    float4 qB[GG];        // {q02, q12, b0,  b1 }
    float4 qC[GG];        // {b2,  a,   0,   0  }
    float4 mf[GG*MM];     // {c, aL, aR, 0} with a = sqrt(0.5*LOG2E)/sigma
    float  we[4];         // even-row upsample taps (x2 folded)
    float  wo[4];         // odd-row upsample taps  (x2 folded)
};

__constant__ Prm c_prm;
__device__   Prm g_prm;
__device__ float g_y[NB*CC*HY*WY];   // downsampled pyramid level (6.3 MB)

__device__ __forceinline__ float softplus_f(float x){
    if (x > 20.f) return x;
    return log1pf(__expf(x));
}
__device__ __forceinline__ float ex2f(float x){
    float y; asm("ex2.approx.ftz.f32 %0, %1;" : "=f"(y) : "f"(x)); return y;
}

__device__ __forceinline__ void gauss7(float* gw){
    float s = 0.f;
    #pragma unroll
    for (int k = 0; k < 7; k++){
        float r = (float)(k - 3);
        gw[k] = __expf(-r*r/(2.f*0.9f*0.9f));
        s += gw[k];
    }
    float is = 1.f/s;
    #pragma unroll
    for (int k = 0; k < 7; k++) gw[k] *= is;
}

// ---------------- setup work (inside down_kernel's extra z-slice) ----------------
__device__ void do_setup(const float* __restrict__ mu,
                         const float* __restrict__ L_raw,
                         const float* __restrict__ pi,
                         const float* __restrict__ mf_c,
                         const float* __restrict__ mf_sL,
                         const float* __restrict__ mf_sR,
                         int t)
{
    float gw[7];
    gauss7(gw);

    if (t == 0){
        // 2D transposed-conv kernel is 4*(g outer g): fold sqrt(4)=2 into EACH 1D stage.
        g_prm.we[0]=2.f*gw[1]; g_prm.we[1]=2.f*gw[3]; g_prm.we[2]=2.f*gw[5]; g_prm.we[3]=0.f;
        g_prm.wo[0]=2.f*gw[0]; g_prm.wo[1]=2.f*gw[2]; g_prm.wo[2]=2.f*gw[4]; g_prm.wo[3]=2.f*gw[6];
    }

    if (t < GG){
        int g = t;
        float pmx = -3.4e38f;
        for (int q = 0; q < GG; q++) pmx = fmaxf(pmx, pi[q]);
        float ps = 0.f;
        for (int q = 0; q < GG; q++) ps += __expf(pi[q] - pmx);
        float lse = pmx + logf(ps);

        float L[3][3];
        for (int i = 0; i < 3; i++)
            for (int j = 0; j < 3; j++)
                L[i][j] = (j < i) ? L_raw[(g*3+i)*3+j] : 0.f;
        for (int i = 0; i < 3; i++)
            L[i][i] = softplus_f(softplus_f(L_raw[(g*3+i)*3+i]) + 1e-4f) + 1e-4f;

        float S[3][3];
        for (int i = 0; i < 3; i++)
            for (int j = 0; j < 3; j++){
                float acc = 0.f;
                for (int k = 0; k < 3; k++) acc += L[i][k]*L[j][k];
                S[i][j] = acc + (i==j ? 1e-4f : 0.f);
            }

        float detS = S[0][0]*(S[1][1]*S[2][2]-S[1][2]*S[1][2])
                   - S[0][1]*(S[0][1]*S[2][2]-S[1][2]*S[0][2])
                   + S[0][2]*(S[0][1]*S[1][2]-S[1][1]*S[0][2]);

        float A00=S[0][0]+1e-3f, A11=S[1][1]+1e-3f, A22=S[2][2]+1e-3f;
        float A01=S[0][1],       A02=S[0][2],       A12=S[1][2];
        float detA = A00*(A11*A22-A12*A12) - A01*(A01*A22-A12*A02) + A02*(A01*A12-A11*A02);
        float id = 1.f/detA;
        float i00 = (A11*A22-A12*A12)*id;
        float i11 = (A00*A22-A02*A02)*id;
        float i22 = (A00*A11-A01*A01)*id;
        float i01 = (A02*A12-A01*A22)*id;
        float i02 = (A01*A12-A02*A11)*id;
        float i12 = (A01*A02-A00*A12)*id;

        // LOG2E-folded coefficients (exp2 domain), -0.5 on diagonals, -1 on crosses
        float q00 = LOG2E*-0.5f*i00, q11 = LOG2E*-0.5f*i11, q22 = LOG2E*-0.5f*i22;
        float q01 = LOG2E*-i01,      q02 = LOG2E*-i02,      q12 = LOG2E*-i12;
        float cw  = LOG2E*(-0.5f*logf(detS) + (pi[g]-lse));
        float m0 = mu[g*3+0], m1 = mu[g*3+1], m2 = mu[g*3+2];

        // expand quadratic around 0: linear + constant terms
        float b0 = -(2.f*q00*m0 + q01*m1 + q02*m2);
        float b1 = -(2.f*q11*m1 + q01*m0 + q12*m2);
        float b2 = -(2.f*q22*m2 + q02*m0 + q12*m1);
        float a  = cw + q00*m0*m0 + q11*m1*m1 + q22*m2*m2
                 + q01*m0*m1 + q02*m0*m2 + q12*m1*m2;

        g_prm.qA[g] = make_float4(q00, q11, q22, q01);
        g_prm.qB[g] = make_float4(q02, q12, b0, b1);
        g_prm.qC[g] = make_float4(b2, a, 0.f, 0.f);
    }

    // membership params: a = sqrt(0.5*LOG2E)/sigma so e_m = exp2(-((r-c)*a)^2)
    if (t < GG*MM){
        float sc = sqrtf(0.5f*LOG2E);
        float sl = softplus_f(mf_sL[t]) + 1e-12f;
        float sr = softplus_f(mf_sR[t]) + 1e-12f;
        g_prm.mf[t] = make_float4(mf_c[t], sc/sl, sc/sr, 0.f);
    }
}

// ---------------- kernel 1: reflect-pad blur downsample (+ setup z-slice) ----------------
// tmp stored even/odd split so the horizontal stride-2 reads become stride-1
#define TMP_O 1104
__global__ __launch_bounds__(256)
void down_kernel(const float* __restrict__ x,
                 const float* __restrict__ mu,
                 const float* __restrict__ L_raw,
                 const float* __restrict__ pi,
                 const float* __restrict__ mf_c,
                 const float* __restrict__ mf_sL,
                 const float* __restrict__ mf_sR)
{
    __shared__ __align__(16) float xs[37][140];
    __shared__ float tmp2[2224];   // E: r*68+qh ; O: TMP_O + r*68+qh

    int t  = threadIdx.x;
    int nc = blockIdx.z;

    if (nc == NB*CC){
        if (blockIdx.x == 0 && blockIdx.y == 0)
            do_setup(mu, L_raw, pi, mf_c, mf_sL, mf_sR, t);
        return;
    }

    int j0 = blockIdx.x * 64;
    int i0 = blockIdx.y * 16;
    const float* xb = x + (size_t)nc * (HH*WW);

    float w[7];
    gauss7(w);

    int r0 = 2*i0 - 3, c0 = 2*j0 - 3;
    int cbase = c0 & ~3;
    int shift = c0 - cbase;
    int lane = t & 31, wrp = t >> 5;

    bool fast = (r0 >= 0) && (r0 + 36 <= 511) && (cbase >= 0) && (cbase + 136 <= 512);

    if (fast){
        for (int idx = t; idx < 37*34; idx += 256){
            int ri = idx / 34, k = idx - ri*34;
            float4 v = __ldcs((const float4*)(xb + (size_t)(r0+ri)*WW + cbase + 4*k));
            *(float4*)&xs[ri][4*k] = v;
        }
    } else {
        for (int ri = wrp; ri < 37; ri += 8){
            int rr = r0 + ri; rr = (rr < 0) ? -rr : ((rr > 511) ? 1022 - rr : rr);
            const float* row = xb + (size_t)rr*WW;
            for (int ci = lane; ci < 133; ci += 32){
                int cc = c0 + ci; cc = (cc < 0) ? -cc : ((cc > 511) ? 1022 - cc : cc);
                xs[ri][ci + shift] = __ldcs(&row[cc]);
            }
        }
    }
    __syncthreads();

    // vertical 7-tap into even/odd-split tmp (warp-per-row, conflict-free STS)
    #pragma unroll
    for (int rep = 0; rep < 2; rep++){
        int r = wrp + 8*rep;
        for (int q = lane; q < 133; q += 32){
            float s = 0.f;
            #pragma unroll
            for (int a = 0; a < 7; a++) s += w[a]*xs[2*r+a][q + shift];
            int addr = ((q & 1) ? TMP_O : 0) + r*68 + (q >> 1);
            tmp2[addr] = s;
        }
    }
    __syncthreads();

    // horizontal 7-tap downsample: all reads stride-1
    float* yb = g_y + (size_t)nc * (HY*WY);
    int jl = t & 63;
    int rb = t >> 6;
    #pragma unroll
    for (int rr = 0; rr < 4; rr++){
        int r = rb*4 + rr;
        const float* E = &tmp2[r*68];
        const float* O = &tmp2[TMP_O + r*68];
        float s = w[0]*E[jl]   + w[1]*O[jl]
                + w[2]*E[jl+1] + w[3]*O[jl+1]
                + w[4]*E[jl+2] + w[5]*O[jl+2]
                + w[6]*E[jl+3];
        yb[(i0+r)*WY + j0 + jl] = s;
    }
}

// ---------------- kernel 2: fused upsample + GMM (Horner) + membership ----------------
// Warp-owned rows: each warp stages & flushes its own output row -> ZERO block syncs
// in the main loop (only __syncwarp between stage and flush).
__global__ __launch_bounds__(256)
void up_gmm_kernel(float* __restrict__ out)
{
    __shared__ float yt[3][19][20];                 // y tile
    __shared__ float rs[3][19][32];                 // horizontal upsample row sums
    __shared__ __align__(16) float stage[8*480];    // per-warp 480-float row stage

    int tx = threadIdx.x, ty = threadIdx.y;
    int v0 = blockIdx.x * 32;
    int u0 = blockIdx.y * 32;
    int n  = blockIdx.z;

    int iy0 = u0/2 - 1, jy0 = v0/2 - 1;

    // yt load: division-free (c,li) walk; lane = column (19 active)
    {
        int c = 0, li = ty;
        #pragma unroll
        for (int rep = 0; rep < 8; rep++){
            if (c < 3 && tx < 19){
                int gi = iy0 + li, gj = jy0 + tx;
                float v = 0.f;
                if ((unsigned)gi < 256u && (unsigned)gj < 256u)
                    v = g_y[((n*3 + c) << 16) + (gi << 8) + gj];
                yt[c][li][tx] = v;
            }
            li += 8; if (li >= 19){ li -= 19; c++; }
        }
    }
    __syncthreads();

    // rs pass: division-free (c,li) walk; lane = output col
    {
        int c = 0, li = ty;
        #pragma unroll
        for (int rep = 0; rep < 8; rep++){
            if (c < 3){
                int vl = tx;
                float s;
                if (vl & 1){
                    int lj = (vl - 1) >> 1;
                    s = c_prm.wo[0]*yt[c][li][lj]   + c_prm.wo[1]*yt[c][li][lj+1]
                      + c_prm.wo[2]*yt[c][li][lj+2] + c_prm.wo[3]*yt[c][li][lj+3];
                } else {
                    int lj = vl >> 1;
                    s = c_prm.we[0]*yt[c][li][lj] + c_prm.we[1]*yt[c][li][lj+1] + c_prm.we[2]*yt[c][li][lj+2];
                }
                rs[c][li][vl] = s;
            }
            li += 8; if (li >= 19){ li -= 19; c++; }
        }
    }
    __syncthreads();

    // per-warp stage segment; stride-15 writes conflict-free (gcd(15,32)=1)
    float* wstage = &stage[ty*480];
    float* st     = wstage + tx*15;

    #pragma unroll
    for (int slab = 0; slab < 2; slab++){
        int p = slab*8 + ty;      // pair: rows 2p (even), 2p+1 (odd)

        // shared vertical taps: 12 LDS serve both pixels of the pair
        float xe[3], xo[3];
        #pragma unroll
        for (int c = 0; c < 3; c++){
            float a0 = rs[c][p  ][tx];
            float a1 = rs[c][p+1][tx];
            float a2 = rs[c][p+2][tx];
            float a3 = rs[c][p+3][tx];
            xe[c] = c_prm.we[0]*a0 + c_prm.we[1]*a1 + c_prm.we[2]*a2;
            xo[c] = c_prm.wo[0]*a0 + c_prm.wo[1]*a1 + c_prm.wo[2]*a2 + c_prm.wo[3]*a3;
        }

        // two phases: even row (2p), odd row (2p+1); warp-private stage/flush
        #pragma unroll
        for (int phase = 0; phase < 2; phase++){
            float x0 = phase ? xo[0] : xe[0];
            float x1 = phase ? xo[1] : xe[1];
            float x2 = phase ? xo[2] : xe[2];

            // GMM logits: Horner-expanded quadratic (9 FMA each), exp2 domain
            float lg[GG];
            float mx = -3.4e38f;
            #pragma unroll
            for (int g = 0; g < GG; g++){
                float4 A = c_prm.qA[g], B = c_prm.qB[g], C = c_prm.qC[g];
                float t0 = fmaf(A.x, x0, B.z);
                t0 = fmaf(A.w, x1, t0);
                t0 = fmaf(B.x, x2, t0);
                float q = fmaf(x0, t0, C.y);
                float t1 = fmaf(A.y, x1, B.w);
                t1 = fmaf(B.y, x2, t1);
                q = fmaf(x1, t1, q);
                float t2 = fmaf(A.z, x2, C.x);
                q = fmaf(x2, t2, q);
                lg[g] = q;
                mx = fmaxf(mx, q);
            }
            float e[GG], ssum = 0.f;
            #pragma unroll
            for (int g = 0; g < GG; g++){ e[g] = ex2f(lg[g] - mx); ssum += e[g]; }
            float inv = __fdividef(1.0f, ssum);

            // membership: direct evaluation, staged to this warp's segment
            #pragma unroll
            for (int g = 0; g < GG; g++){
                float r = e[g]*inv;
                float es[MM], s2 = 0.f;
                #pragma unroll
                for (int m = 0; m < MM; m++){
                    float4 pm = c_prm.mf[g*MM+m];
                    float a = (r < pm.x) ? pm.y : pm.z;
                    float d = (r - pm.x)*a;
                    es[m] = ex2f(-d*d);
                    s2 += es[m];
                }
                float inv2 = __fdividef(1.0f, s2);
                st[g*3+0] = es[0]*inv2;
                st[g*3+1] = es[1]*inv2;
                st[g*3+2] = es[2]*inv2;
            }
            __syncwarp();

            // warp flushes its own row: 120 contiguous float4, fully coalesced
            {
                int u = u0 + 2*p + phase;
                float* rowOut = out + (((size_t)(n*512 + u))*512 + v0)*15;
                __stcs((float4*)(rowOut + 4*tx),        *(const float4*)(wstage + 4*tx));
                __stcs((float4*)(rowOut + 4*(tx+32)),   *(const float4*)(wstage + 4*(tx+32)));
                __stcs((float4*)(rowOut + 4*(tx+64)),   *(const float4*)(wstage + 4*(tx+64)));
                if (tx < 24)
                    __stcs((float4*)(rowOut + 4*(tx+96)), *(const float4*)(wstage + 4*(tx+96)));
            }
            __syncwarp();
        }
    }
}

// ---------------- launch ----------------
extern "C" void kernel_launch(void* const* d_in, const int* in_sizes, int n_in,
                              void* d_out, int out_size)
{
    (void)in_sizes; (void)n_in; (void)out_size;
    const float* x     = (const float*)d_in[0];
    const float* mu    = (const float*)d_in[1];
    const float* L_raw = (const float*)d_in[2];
    const float* pi    = (const float*)d_in[3];
    const float* mf_c  = (const float*)d_in[4];
    const float* mf_sL = (const float*)d_in[5];
    const float* mf_sR = (const float*)d_in[6];
    float* out = (float*)d_out;

    down_kernel<<<dim3(WY/64, HY/16, NB*CC + 1), 256>>>(x, mu, L_raw, pi, mf_c, mf_sL, mf_sR);

    void* src = nullptr;
    cudaGetSymbolAddress(&src, g_prm);
    cudaMemcpyToSymbolAsync(c_prm, src, sizeof(Prm), 0, cudaMemcpyDeviceToDevice, 0);

    up_gmm_kernel<<<dim3(WW/32, HH/32, NB), dim3(32, 8)>>>(out);
}